// round 2
// baseline (speedup 1.0000x reference)
#include <cuda_runtime.h>
#include <math.h>

#define NN 40
#define BB 32
#define DD 768
#define TT 820
#define MAXM 49920   // outside L=1: 40*39*32 combos

// ---------------- static scratch (no allocations allowed) ----------------
__device__ float g_iv [(size_t)TT * BB * DD];        // inside vectors
__device__ float g_ov [(size_t)TT * BB * DD];        // outside vectors
__device__ float g_isc[TT * BB];                     // inside scores
__device__ float g_osc[TT * BB];                     // outside scores
__device__ float g_P  [(size_t)TT * BB * 3 * DD];    // [Pl | Pr | R] per cell/batch
__device__ float g_Po [(size_t)TT * BB * DD];        // ov @ W1a^T
__device__ float g_H  [(size_t)MAXM * DD];           // hidden scratch
__device__ float g_V  [(size_t)MAXM * DD];           // compose output scratch
__device__ float g_S  [MAXM];                        // scores scratch
__device__ float g_Wcat[3 * DD * DD];                // rows: W1a | W1b | W_bil

__host__ __device__ __forceinline__ int offL(int L) {
    return TT - (42 - L) * (41 - L) / 2;   // first chart index of spans of length L
}

__device__ __forceinline__ float blockReduce256(float v) {
    __shared__ float sh[8];
    int lane = threadIdx.x & 31, w = threadIdx.x >> 5;
    #pragma unroll
    for (int o = 16; o; o >>= 1) v += __shfl_down_sync(0xffffffffu, v, o);
    __syncthreads();
    if (lane == 0) sh[w] = v;
    __syncthreads();
    if (threadIdx.x == 0) {
        float s = 0.f;
        #pragma unroll
        for (int i = 0; i < 8; i++) s += sh[i];
        v = s;
    }
    __syncthreads();
    return v;   // valid in thread 0
}

// ---------------- init kernels ----------------
__global__ void k_init_sc() {
    int i = blockIdx.x * 256 + threadIdx.x;
    if (i < TT * BB) { g_isc[i] = 0.f; g_osc[i] = 0.f; }
}
__global__ void k_copy_base(const float* __restrict__ src) {
    size_t i = (size_t)blockIdx.x * 256 + threadIdx.x;
    if (i < (size_t)NN * BB * DD) g_iv[i] = src[i];
}
__global__ void k_root(const float* __restrict__ rb) {
    int i = blockIdx.x * 256 + threadIdx.x;
    if (i < BB * DD) g_ov[(size_t)offL(NN) * BB * DD + i] = rb[i % DD];
}
__global__ void k_build_wcat(const float* __restrict__ W1, const float* __restrict__ Wb) {
    int i = blockIdx.x * 256 + threadIdx.x;
    if (i >= 3 * DD * DD) return;
    int j = i / DD, k = i % DD;
    float v;
    if (j < DD)            v = W1[(size_t)j * (2 * DD) + k];            // W1a: W1[j, k]
    else if (j < 2 * DD)   v = W1[(size_t)(j - DD) * (2 * DD) + DD + k];// W1b: W1[j, D+k]
    else                   v = Wb[(size_t)(j - 2 * DD) * DD + k];       // W_bil[j, k]
    g_Wcat[i] = v;
}
__global__ void k_zero_out(float* out) { if (threadIdx.x == 0) out[0] = 0.f; }

// ---------------- generic fp32 GEMM:  C[m,n] = act( sum_k A[m,k]*W[n,k] + bias[n] )
__global__ __launch_bounds__(256) void k_gemm(
    const float* __restrict__ A, int lda,
    const float* __restrict__ W, int ldw,
    const float* __restrict__ bias,
    float* __restrict__ C, int ldc,
    int M, int N, int K, int doRelu)
{
    __shared__ float As[8][128];
    __shared__ float Bs[8][128];
    int tid = threadIdx.x;
    int tx = tid & 15, ty = tid >> 4;
    int m0 = blockIdx.y * 128;
    int n0 = blockIdx.x * 128;
    int lr = tid >> 1;
    int lk = (tid & 1) * 4;
    float acc[8][8];
    #pragma unroll
    for (int i = 0; i < 8; i++)
        #pragma unroll
        for (int j = 0; j < 8; j++) acc[i][j] = 0.f;

    const float* ap = A + (size_t)(m0 + lr) * lda + lk;
    const float* wp = W + (size_t)(n0 + lr) * ldw + lk;   // N is multiple of 128 -> always valid
    bool aok = (m0 + lr) < M;

    for (int k0 = 0; k0 < K; k0 += 8) {
        float4 av = make_float4(0.f, 0.f, 0.f, 0.f);
        if (aok) av = *(const float4*)(ap + k0);
        float4 bv = *(const float4*)(wp + k0);
        As[lk + 0][lr] = av.x; As[lk + 1][lr] = av.y; As[lk + 2][lr] = av.z; As[lk + 3][lr] = av.w;
        Bs[lk + 0][lr] = bv.x; Bs[lk + 1][lr] = bv.y; Bs[lk + 2][lr] = bv.z; Bs[lk + 3][lr] = bv.w;
        __syncthreads();
        #pragma unroll
        for (int kk = 0; kk < 8; kk++) {
            float a[8], b[8];
            *(float4*)(a)     = *(const float4*)(&As[kk][ty * 8]);
            *(float4*)(a + 4) = *(const float4*)(&As[kk][ty * 8 + 4]);
            *(float4*)(b)     = *(const float4*)(&Bs[kk][tx * 8]);
            *(float4*)(b + 4) = *(const float4*)(&Bs[kk][tx * 8 + 4]);
            #pragma unroll
            for (int i = 0; i < 8; i++)
                #pragma unroll
                for (int j = 0; j < 8; j++)
                    acc[i][j] += a[i] * b[j];
        }
        __syncthreads();
    }
    float bvals[8];
    #pragma unroll
    for (int j = 0; j < 8; j++) bvals[j] = bias ? bias[n0 + tx * 8 + j] : 0.f;
    #pragma unroll
    for (int i = 0; i < 8; i++) {
        int m = m0 + ty * 8 + i;
        if (m < M) {
            float* crow = C + (size_t)m * ldc + n0 + tx * 8;
            float o[8];
            #pragma unroll
            for (int j = 0; j < 8; j++) {
                float v = acc[i][j] + bvals[j];
                o[j] = doRelu ? fmaxf(v, 0.f) : v;
            }
            *(float4*)(crow)     = *(float4*)(o);
            *(float4*)(crow + 4) = *(float4*)(o + 4);
        }
    }
}

// ---------------- per-combo combine: H = relu(Pl+Pr+b1), S = l.W.r + isc + isc
__global__ __launch_bounds__(256) void k_comb_inside(int L, int nb, int ns,
                                                     const float* __restrict__ b1) {
    int rid = blockIdx.x;
    int batch = rid % BB;
    int t = rid / BB;
    int si = t % ns;
    int b = t / ns;
    int s = si + 1;
    int il = offL(s) + b;
    int ir = offL(L - s) + b + s;
    const float* pl  = g_P + ((size_t)il * BB + batch) * (3 * DD);
    const float* prr = g_P + ((size_t)ir * BB + batch) * (3 * DD);
    const float* xl  = g_iv + ((size_t)il * BB + batch) * DD;
    float* hrow = g_H + (size_t)rid * DD;
    float dot = 0.f;
    for (int d = threadIdx.x; d < DD; d += 256) {
        float h = pl[d] + prr[DD + d] + b1[d];
        hrow[d] = h > 0.f ? h : 0.f;
        dot += xl[d] * prr[2 * DD + d];
    }
    dot = blockReduce256(dot);
    if (threadIdx.x == 0)
        g_S[rid] = dot + g_isc[il * BB + batch] + g_isc[ir * BB + batch];
}

__global__ __launch_bounds__(256) void k_comb_outside(int L, int nb, int nso,
                                                      const float* __restrict__ b1) {
    int rid = blockIdx.x;
    int batch = rid % BB;
    int t = rid / BB;
    int k = t % nso;
    int b = t / nso;
    int ip, isx;
    if (k < b) {
        int c = k;
        ip  = offL(b + L - c) + c;   // parent span (c, b+L)
        isx = offL(b - c) + c;       // sibling (c, b)
    } else {
        int c = b + L + 1 + (k - b);
        ip  = offL(c - b) + b;       // parent span (b, c)
        isx = offL(c - b - L) + b + L; // sibling (b+L, c)
    }
    const float* pl  = g_Po + ((size_t)ip * BB + batch) * DD;
    const float* prr = g_P  + ((size_t)isx * BB + batch) * (3 * DD);
    const float* xp  = g_ov + ((size_t)ip * BB + batch) * DD;
    float* hrow = g_H + (size_t)rid * DD;
    float dot = 0.f;
    for (int d = threadIdx.x; d < DD; d += 256) {
        float h = pl[d] + prr[DD + d] + b1[d];
        hrow[d] = h > 0.f ? h : 0.f;
        dot += xp[d] * prr[2 * DD + d];
    }
    dot = blockReduce256(dot);
    if (threadIdx.x == 0)
        g_S[rid] = dot + g_osc[ip * BB + batch] + g_isc[isx * BB + batch];
}

// ---------------- softmax over splits + weighted mix into chart cell
__global__ __launch_bounds__(256) void k_smx(int ns, int cell0,
                                             const float* __restrict__ V,
                                             float* __restrict__ vout,
                                             float* __restrict__ scout) {
    int bid = blockIdx.x;
    int batch = bid % BB;
    int b = bid / BB;
    __shared__ float sv[40], wv[40];
    int base = (b * ns) * BB + batch;   // row for split s = base + s*BB
    if (threadIdx.x < ns) sv[threadIdx.x] = g_S[base + threadIdx.x * BB];
    __syncthreads();
    if (threadIdx.x == 0) {
        float mx = -1e30f;
        for (int s = 0; s < ns; s++) mx = fmaxf(mx, sv[s]);
        float Z = 0.f;
        for (int s = 0; s < ns; s++) { float e = expf(sv[s] - mx); wv[s] = e; Z += e; }
        float inv = 1.f / Z, sc = 0.f;
        for (int s = 0; s < ns; s++) { wv[s] *= inv; sc += wv[s] * sv[s]; }
        scout[(cell0 + b) * BB + batch] = sc;
    }
    __syncthreads();
    float* orow = vout + ((size_t)(cell0 + b) * BB + batch) * DD;
    for (int d = threadIdx.x; d < DD; d += 256) {
        float acc = 0.f;
        for (int s = 0; s < ns; s++)
            acc += wv[s] * V[(size_t)(base + s * BB) * DD + d];
        orow[d] = acc;
    }
}

// ---------------- final cosine loss ----------------
__global__ __launch_bounds__(256) void k_loss(const float* __restrict__ base,
                                              float* __restrict__ out) {
    int bid = blockIdx.x;
    int batch = bid % BB;
    int n = bid / BB;
    const float* tv = g_ov + ((size_t)n * BB + batch) * DD;
    const float* bv = base + ((size_t)n * BB + batch) * DD;
    float dp = 0.f, n1 = 0.f, n2 = 0.f;
    for (int d = threadIdx.x; d < DD; d += 256) {
        float a = tv[d], c = bv[d];
        dp += a * c; n1 += a * a; n2 += c * c;
    }
    dp = blockReduce256(dp);
    n1 = blockReduce256(n1);
    n2 = blockReduce256(n2);
    if (threadIdx.x == 0) {
        float den = fmaxf(sqrtf(n1) * sqrtf(n2), 1e-8f);
        atomicAdd(out, (1.f - dp / den) * (1.f / (NN * BB)));
    }
}

// ---------------- host launcher ----------------
extern "C" void kernel_launch(void* const* d_in, const int* in_sizes, int n_in,
                              void* d_out, int out_size) {
    const float* base = (const float*)d_in[0];
    const float* Wbil = (const float*)d_in[1];
    const float* W1   = (const float*)d_in[2];
    const float* b1   = (const float*)d_in[3];
    const float* W2   = (const float*)d_in[4];
    const float* b2   = (const float*)d_in[5];
    const float* rootb= (const float*)d_in[6];
    float* out = (float*)d_out;

    float *p_iv, *p_ov, *p_isc, *p_osc, *p_P, *p_Po, *p_H, *p_V, *p_Wcat;
    cudaGetSymbolAddress((void**)&p_iv,  g_iv);
    cudaGetSymbolAddress((void**)&p_ov,  g_ov);
    cudaGetSymbolAddress((void**)&p_isc, g_isc);
    cudaGetSymbolAddress((void**)&p_osc, g_osc);
    cudaGetSymbolAddress((void**)&p_P,   g_P);
    cudaGetSymbolAddress((void**)&p_Po,  g_Po);
    cudaGetSymbolAddress((void**)&p_H,   g_H);
    cudaGetSymbolAddress((void**)&p_V,   g_V);
    cudaGetSymbolAddress((void**)&p_Wcat,g_Wcat);

    k_init_sc   <<<(TT * BB + 255) / 256, 256>>>();
    k_copy_base <<<(NN * BB * DD + 255) / 256, 256>>>(base);
    k_root      <<<(BB * DD + 255) / 256, 256>>>(rootb);
    k_build_wcat<<<(3 * DD * DD + 255) / 256, 256>>>(W1, Wbil);

    // projections for base cells (cells 0..N-1)
    k_gemm<<<dim3(3 * DD / 128, (NN * BB + 127) / 128), 256>>>(
        p_iv, DD, p_Wcat, DD, nullptr, p_P, 3 * DD, NN * BB, 3 * DD, DD, 0);

    // ---------------- inside pass ----------------
    for (int L = 2; L <= NN; L++) {
        int nb = NN + 1 - L, ns = L - 1;
        int M = nb * ns * BB;
        k_comb_inside<<<M, 256>>>(L, nb, ns, b1);
        k_gemm<<<dim3(DD / 128, (M + 127) / 128), 256>>>(
            p_H, DD, W2, DD, b2, p_V, DD, M, DD, DD, 1);
        k_smx<<<nb * BB, 256>>>(ns, offL(L), p_V, p_iv, p_isc);
        if (L < NN) {
            size_t c0 = (size_t)offL(L);
            k_gemm<<<dim3(3 * DD / 128, (nb * BB + 127) / 128), 256>>>(
                p_iv + c0 * BB * DD, DD, p_Wcat, DD, nullptr,
                p_P + c0 * BB * 3 * DD, 3 * DD, nb * BB, 3 * DD, DD, 0);
        }
    }

    // root outside projection Po = ov_root @ W1a^T
    {
        size_t c0 = (size_t)offL(NN);
        k_gemm<<<dim3(DD / 128, 1), 256>>>(
            p_ov + c0 * BB * DD, DD, p_Wcat, DD, nullptr,
            p_Po + c0 * BB * DD, DD, BB, DD, DD, 0);
    }

    // ---------------- outside pass ----------------
    for (int L = NN - 1; L >= 1; L--) {
        int nb = NN + 1 - L, nso = NN - L;
        int M = nb * nso * BB;
        k_comb_outside<<<M, 256>>>(L, nb, nso, b1);
        k_gemm<<<dim3(DD / 128, (M + 127) / 128), 256>>>(
            p_H, DD, W2, DD, b2, p_V, DD, M, DD, DD, 1);
        k_smx<<<nb * BB, 256>>>(nso, offL(L), p_V, p_ov, p_osc);
        if (L > 1) {
            size_t c0 = (size_t)offL(L);
            k_gemm<<<dim3(DD / 128, (nb * BB + 127) / 128), 256>>>(
                p_ov + c0 * BB * DD, DD, p_Wcat, DD, nullptr,
                p_Po + c0 * BB * DD, DD, nb * BB, DD, DD, 0);
        }
    }

    k_zero_out<<<1, 1>>>(out);
    k_loss<<<NN * BB, 256>>>(base, out);
}

// round 4
// speedup vs baseline: 1.2297x; 1.2297x over previous
#include <cuda_runtime.h>
#include <math.h>
#include <stdint.h>

#define NN 40
#define BB 32
#define DD 768
#define TT 820
#define MAXM 49920   // outside L=1: 40*39*32 combos

// ---------------- static scratch (no allocations allowed) ----------------
__device__ float g_iv [(size_t)TT * BB * DD];        // inside vectors
__device__ float g_ov [(size_t)TT * BB * DD];        // outside vectors
__device__ float g_isc[TT * BB];                     // inside scores
__device__ float g_osc[TT * BB];                     // outside scores
__device__ float g_P  [(size_t)TT * BB * 3 * DD];    // [Pl | Pr | R] per cell/batch
__device__ float g_Po [(size_t)TT * BB * DD];        // ov @ W1a^T
__device__ float g_H  [(size_t)MAXM * DD];           // hidden scratch
__device__ float g_V  [(size_t)MAXM * DD];           // compose output scratch
__device__ float g_S  [MAXM];                        // scores scratch
__device__ float g_Wcat[3 * DD * DD];                // rows: W1a | W1b | W_bil

__host__ __device__ __forceinline__ int offL(int L) {
    return TT - (42 - L) * (41 - L) / 2;   // first chart index of spans of length L
}

__device__ __forceinline__ float blockReduce256(float v) {
    __shared__ float sh[8];
    int lane = threadIdx.x & 31, w = threadIdx.x >> 5;
    #pragma unroll
    for (int o = 16; o; o >>= 1) v += __shfl_down_sync(0xffffffffu, v, o);
    __syncthreads();
    if (lane == 0) sh[w] = v;
    __syncthreads();
    if (threadIdx.x == 0) {
        float s = 0.f;
        #pragma unroll
        for (int i = 0; i < 8; i++) s += sh[i];
        v = s;
    }
    __syncthreads();
    return v;   // valid in thread 0
}

// ---------------- init kernels ----------------
__global__ void k_init_sc() {
    int i = blockIdx.x * 256 + threadIdx.x;
    if (i < TT * BB) { g_isc[i] = 0.f; g_osc[i] = 0.f; }
}
__global__ void k_copy_base(const float* __restrict__ src) {
    size_t i = (size_t)blockIdx.x * 256 + threadIdx.x;
    if (i < (size_t)NN * BB * DD) g_iv[i] = src[i];
}
__global__ void k_root(const float* __restrict__ rb) {
    int i = blockIdx.x * 256 + threadIdx.x;
    if (i < BB * DD) g_ov[(size_t)offL(NN) * BB * DD + i] = rb[i % DD];
}
__global__ void k_build_wcat(const float* __restrict__ W1, const float* __restrict__ Wb) {
    int i = blockIdx.x * 256 + threadIdx.x;
    if (i >= 3 * DD * DD) return;
    int j = i / DD, k = i % DD;
    float v;
    if (j < DD)            v = W1[(size_t)j * (2 * DD) + k];            // W1a: W1[j, k]
    else if (j < 2 * DD)   v = W1[(size_t)(j - DD) * (2 * DD) + DD + k];// W1b: W1[j, D+k]
    else                   v = Wb[(size_t)(j - 2 * DD) * DD + k];       // W_bil[j, k]
    g_Wcat[i] = v;
}
__global__ void k_zero_out(float* out) { if (threadIdx.x == 0) out[0] = 0.f; }

// ---------------- tensor-core helpers ----------------
__device__ __forceinline__ uint32_t tf32hi(float x) {
    uint32_t r;
    asm("cvt.rna.tf32.f32 %0, %1;" : "=r"(r) : "f"(x));
    return r;
}
__device__ __forceinline__ void mma8(float* c, const uint32_t* a, uint32_t b0, uint32_t b1) {
    asm volatile(
        "mma.sync.aligned.m16n8k8.row.col.f32.tf32.tf32.f32 "
        "{%0,%1,%2,%3},{%4,%5,%6,%7},{%8,%9},{%0,%1,%2,%3};"
        : "+f"(c[0]), "+f"(c[1]), "+f"(c[2]), "+f"(c[3])
        : "r"(a[0]), "r"(a[1]), "r"(a[2]), "r"(a[3]), "r"(b0), "r"(b1));
}

// ---------------- tensor-core GEMM (3xTF32, ~fp32 accurate) ----------------
//  C[m,n] = act( sum_k A[m,k]*W[n,k] + bias[n] )
//  requires: K % 32 == 0, N % 128 == 0
#define KC 32
#define KPAD (KC + 4)
__global__ __launch_bounds__(256) void k_gemm_tc(
    const float* __restrict__ A, int lda,
    const float* __restrict__ W, int ldw,
    const float* __restrict__ bias,
    float* __restrict__ C, int ldc,
    int M, int N, int K, int doRelu)
{
    __shared__ float As[128][KPAD];   // [m][k]
    __shared__ float Bs[128][KPAD];   // [n][k]
    int tid = threadIdx.x;
    int warp = tid >> 5, lane = tid & 31;
    int m0 = blockIdx.y * 128, n0 = blockIdx.x * 128;
    int wm = (warp >> 2) * 64;        // warp m offset within tile
    int wn = (warp & 3) * 32;         // warp n offset within tile
    int g = lane >> 2, tg = lane & 3; // groupID, thread-in-group

    float acc[4][4][4];               // [mtile][ntile][frag]
    #pragma unroll
    for (int i = 0; i < 4; i++)
        #pragma unroll
        for (int j = 0; j < 4; j++)
            #pragma unroll
            for (int c = 0; c < 4; c++) acc[i][j][c] = 0.f;

    int lrow = tid >> 1;
    int lk = (tid & 1) * 16;
    const float* aptr = A + (size_t)(m0 + lrow) * lda + lk;
    const float* wptr = W + (size_t)(n0 + lrow) * ldw + lk;
    bool aok = (m0 + lrow) < M;

    for (int k0 = 0; k0 < K; k0 += KC) {
        #pragma unroll
        for (int i = 0; i < 4; i++) {
            float4 av = make_float4(0.f, 0.f, 0.f, 0.f);
            if (aok) av = *(const float4*)(aptr + k0 + i * 4);
            *(float4*)&As[lrow][lk + i * 4] = av;
            float4 bv = *(const float4*)(wptr + k0 + i * 4);
            *(float4*)&Bs[lrow][lk + i * 4] = bv;
        }
        __syncthreads();

        #pragma unroll
        for (int ks = 0; ks < KC; ks += 8) {
            // A fragments (hi/lo split)
            uint32_t ahi[4][4], alo[4][4];
            #pragma unroll
            for (int mt = 0; mt < 4; mt++) {
                int r = wm + mt * 16 + g;
                float f0 = As[r][ks + tg];
                float f1 = As[r + 8][ks + tg];
                float f2 = As[r][ks + tg + 4];
                float f3 = As[r + 8][ks + tg + 4];
                ahi[mt][0] = tf32hi(f0); alo[mt][0] = __float_as_uint(f0 - __uint_as_float(ahi[mt][0]));
                ahi[mt][1] = tf32hi(f1); alo[mt][1] = __float_as_uint(f1 - __uint_as_float(ahi[mt][1]));
                ahi[mt][2] = tf32hi(f2); alo[mt][2] = __float_as_uint(f2 - __uint_as_float(ahi[mt][2]));
                ahi[mt][3] = tf32hi(f3); alo[mt][3] = __float_as_uint(f3 - __uint_as_float(ahi[mt][3]));
            }
            #pragma unroll
            for (int nt = 0; nt < 4; nt++) {
                int c = wn + nt * 8 + g;
                float g0 = Bs[c][ks + tg];
                float g1 = Bs[c][ks + tg + 4];
                uint32_t bh0 = tf32hi(g0), bl0 = __float_as_uint(g0 - __uint_as_float(bh0));
                uint32_t bh1 = tf32hi(g1), bl1 = __float_as_uint(g1 - __uint_as_float(bh1));
                #pragma unroll
                for (int mt = 0; mt < 4; mt++) {
                    mma8(acc[mt][nt], alo[mt], bh0, bh1);   // a_lo * b_hi
                    mma8(acc[mt][nt], ahi[mt], bl0, bl1);   // a_hi * b_lo
                    mma8(acc[mt][nt], ahi[mt], bh0, bh1);   // a_hi * b_hi (last: biggest term)
                }
            }
        }
        __syncthreads();
    }

    // epilogue: bias + optional relu, float2 stores
    #pragma unroll
    for (int mt = 0; mt < 4; mt++) {
        int r0 = m0 + wm + mt * 16 + g;
        #pragma unroll
        for (int nt = 0; nt < 4; nt++) {
            int cc = n0 + wn + nt * 8 + tg * 2;
            float bx = bias ? bias[cc] : 0.f;
            float by = bias ? bias[cc + 1] : 0.f;
            float v0 = acc[mt][nt][0] + bx, v1 = acc[mt][nt][1] + by;
            float v2 = acc[mt][nt][2] + bx, v3 = acc[mt][nt][3] + by;
            if (doRelu) {
                v0 = fmaxf(v0, 0.f); v1 = fmaxf(v1, 0.f);
                v2 = fmaxf(v2, 0.f); v3 = fmaxf(v3, 0.f);
            }
            if (r0 < M)     *(float2*)(C + (size_t)r0 * ldc + cc)       = make_float2(v0, v1);
            if (r0 + 8 < M) *(float2*)(C + (size_t)(r0 + 8) * ldc + cc) = make_float2(v2, v3);
        }
    }
}

// ---------------- per-combo combine: H = relu(Pl+Pr+b1), S = l.W.r + isc + isc
__global__ __launch_bounds__(256) void k_comb_inside(int L, int nb, int ns,
                                                     const float* __restrict__ b1) {
    int rid = blockIdx.x;
    int batch = rid % BB;
    int t = rid / BB;
    int si = t % ns;
    int b = t / ns;
    int s = si + 1;
    int il = offL(s) + b;
    int ir = offL(L - s) + b + s;
    const float* pl  = g_P + ((size_t)il * BB + batch) * (3 * DD);
    const float* prr = g_P + ((size_t)ir * BB + batch) * (3 * DD);
    const float* xl  = g_iv + ((size_t)il * BB + batch) * DD;
    float* hrow = g_H + (size_t)rid * DD;
    float dot = 0.f;
    for (int d = threadIdx.x; d < DD; d += 256) {
        float h = pl[d] + prr[DD + d] + b1[d];
        hrow[d] = h > 0.f ? h : 0.f;
        dot += xl[d] * prr[2 * DD + d];
    }
    dot = blockReduce256(dot);
    if (threadIdx.x == 0)
        g_S[rid] = dot + g_isc[il * BB + batch] + g_isc[ir * BB + batch];
}

__global__ __launch_bounds__(256) void k_comb_outside(int L, int nb, int nso,
                                                      const float* __restrict__ b1) {
    int rid = blockIdx.x;
    int batch = rid % BB;
    int t = rid / BB;
    int k = t % nso;
    int b = t / nso;
    int ip, isx;
    if (k < b) {
        int c = k;
        ip  = offL(b + L - c) + c;   // parent span (c, b+L)
        isx = offL(b - c) + c;       // sibling (c, b)
    } else {
        int c = b + L + 1 + (k - b);
        ip  = offL(c - b) + b;       // parent span (b, c)
        isx = offL(c - b - L) + b + L; // sibling (b+L, c)
    }
    const float* pl  = g_Po + ((size_t)ip * BB + batch) * DD;
    const float* prr = g_P  + ((size_t)isx * BB + batch) * (3 * DD);
    const float* xp  = g_ov + ((size_t)ip * BB + batch) * DD;
    float* hrow = g_H + (size_t)rid * DD;
    float dot = 0.f;
    for (int d = threadIdx.x; d < DD; d += 256) {
        float h = pl[d] + prr[DD + d] + b1[d];
        hrow[d] = h > 0.f ? h : 0.f;
        dot += xp[d] * prr[2 * DD + d];
    }
    dot = blockReduce256(dot);
    if (threadIdx.x == 0)
        g_S[rid] = dot + g_osc[ip * BB + batch] + g_isc[isx * BB + batch];
}

// ---------------- softmax over splits + weighted mix into chart cell
__global__ __launch_bounds__(256) void k_smx(int ns, int cell0,
                                             const float* __restrict__ V,
                                             float* __restrict__ vout,
                                             float* __restrict__ scout) {
    int bid = blockIdx.x;
    int batch = bid % BB;
    int b = bid / BB;
    __shared__ float sv[40], wv[40];
    int base = (b * ns) * BB + batch;   // row for split s = base + s*BB
    if (threadIdx.x < ns) sv[threadIdx.x] = g_S[base + threadIdx.x * BB];
    __syncthreads();
    if (threadIdx.x == 0) {
        float mx = -1e30f;
        for (int s = 0; s < ns; s++) mx = fmaxf(mx, sv[s]);
        float Z = 0.f;
        for (int s = 0; s < ns; s++) { float e = expf(sv[s] - mx); wv[s] = e; Z += e; }
        float inv = 1.f / Z, sc = 0.f;
        for (int s = 0; s < ns; s++) { wv[s] *= inv; sc += wv[s] * sv[s]; }
        scout[(cell0 + b) * BB + batch] = sc;
    }
    __syncthreads();
    float* orow = vout + ((size_t)(cell0 + b) * BB + batch) * DD;
    for (int d = threadIdx.x; d < DD; d += 256) {
        float acc = 0.f;
        for (int s = 0; s < ns; s++)
            acc += wv[s] * V[(size_t)(base + s * BB) * DD + d];
        orow[d] = acc;
    }
}

// ---------------- final cosine loss ----------------
__global__ __launch_bounds__(256) void k_loss(const float* __restrict__ base,
                                              float* __restrict__ out) {
    int bid = blockIdx.x;
    int batch = bid % BB;
    int n = bid / BB;
    const float* tv = g_ov + ((size_t)n * BB + batch) * DD;
    const float* bv = base + ((size_t)n * BB + batch) * DD;
    float dp = 0.f, n1 = 0.f, n2 = 0.f;
    for (int d = threadIdx.x; d < DD; d += 256) {
        float a = tv[d], c = bv[d];
        dp += a * c; n1 += a * a; n2 += c * c;
    }
    dp = blockReduce256(dp);
    n1 = blockReduce256(n1);
    n2 = blockReduce256(n2);
    if (threadIdx.x == 0) {
        float den = fmaxf(sqrtf(n1) * sqrtf(n2), 1e-8f);
        atomicAdd(out, (1.f - dp / den) * (1.f / (NN * BB)));
    }
}

// ---------------- host launcher ----------------
extern "C" void kernel_launch(void* const* d_in, const int* in_sizes, int n_in,
                              void* d_out, int out_size) {
    const float* base = (const float*)d_in[0];
    const float* Wbil = (const float*)d_in[1];
    const float* W1   = (const float*)d_in[2];
    const float* b1   = (const float*)d_in[3];
    const float* W2   = (const float*)d_in[4];
    const float* b2   = (const float*)d_in[5];
    const float* rootb= (const float*)d_in[6];
    float* out = (float*)d_out;

    float *p_iv, *p_ov, *p_isc, *p_osc, *p_P, *p_Po, *p_H, *p_V, *p_Wcat;
    cudaGetSymbolAddress((void**)&p_iv,  g_iv);
    cudaGetSymbolAddress((void**)&p_ov,  g_ov);
    cudaGetSymbolAddress((void**)&p_isc, g_isc);
    cudaGetSymbolAddress((void**)&p_osc, g_osc);
    cudaGetSymbolAddress((void**)&p_P,   g_P);
    cudaGetSymbolAddress((void**)&p_Po,  g_Po);
    cudaGetSymbolAddress((void**)&p_H,   g_H);
    cudaGetSymbolAddress((void**)&p_V,   g_V);
    cudaGetSymbolAddress((void**)&p_Wcat,g_Wcat);

    k_init_sc   <<<(TT * BB + 255) / 256, 256>>>();
    k_copy_base <<<(NN * BB * DD + 255) / 256, 256>>>(base);
    k_root      <<<(BB * DD + 255) / 256, 256>>>(rootb);
    k_build_wcat<<<(3 * DD * DD + 255) / 256, 256>>>(W1, Wbil);

    // projections for base cells (cells 0..N-1)
    k_gemm_tc<<<dim3(3 * DD / 128, (NN * BB + 127) / 128), 256>>>(
        p_iv, DD, p_Wcat, DD, nullptr, p_P, 3 * DD, NN * BB, 3 * DD, DD, 0);

    // ---------------- inside pass ----------------
    for (int L = 2; L <= NN; L++) {
        int nb = NN + 1 - L, ns = L - 1;
        int M = nb * ns * BB;
        k_comb_inside<<<M, 256>>>(L, nb, ns, b1);
        k_gemm_tc<<<dim3(DD / 128, (M + 127) / 128), 256>>>(
            p_H, DD, W2, DD, b2, p_V, DD, M, DD, DD, 1);
        k_smx<<<nb * BB, 256>>>(ns, offL(L), p_V, p_iv, p_isc);
        if (L < NN) {
            size_t c0 = (size_t)offL(L);
            k_gemm_tc<<<dim3(3 * DD / 128, (nb * BB + 127) / 128), 256>>>(
                p_iv + c0 * BB * DD, DD, p_Wcat, DD, nullptr,
                p_P + c0 * BB * 3 * DD, 3 * DD, nb * BB, 3 * DD, DD, 0);
        }
    }

    // root outside projection Po = ov_root @ W1a^T
    {
        size_t c0 = (size_t)offL(NN);
        k_gemm_tc<<<dim3(DD / 128, 1), 256>>>(
            p_ov + c0 * BB * DD, DD, p_Wcat, DD, nullptr,
            p_Po + c0 * BB * DD, DD, BB, DD, DD, 0);
    }

    // ---------------- outside pass ----------------
    for (int L = NN - 1; L >= 1; L--) {
        int nb = NN + 1 - L, nso = NN - L;
        int M = nb * nso * BB;
        k_comb_outside<<<M, 256>>>(L, nb, nso, b1);
        k_gemm_tc<<<dim3(DD / 128, (M + 127) / 128), 256>>>(
            p_H, DD, W2, DD, b2, p_V, DD, M, DD, DD, 1);
        k_smx<<<nb * BB, 256>>>(nso, offL(L), p_V, p_ov, p_osc);
        if (L > 1) {
            size_t c0 = (size_t)offL(L);
            k_gemm_tc<<<dim3(DD / 128, (nb * BB + 127) / 128), 256>>>(
                p_ov + c0 * BB * DD, DD, p_Wcat, DD, nullptr,
                p_Po + c0 * BB * DD, DD, nb * BB, DD, DD, 0);
        }
    }

    k_zero_out<<<1, 1>>>(out);
    k_loss<<<NN * BB, 256>>>(base, out);
}

// round 5
// speedup vs baseline: 2.1368x; 1.7377x over previous
#include <cuda_runtime.h>
#include <math.h>
#include <stdint.h>

#define NN 40
#define BB 32
#define DD 768
#define TT 820
#define MAXM 49920   // outside L=1: 40*39*32 combos

// ---------------- static scratch (no allocations allowed) ----------------
__device__ float g_iv [(size_t)TT * BB * DD];        // inside vectors
__device__ float g_ov [(size_t)TT * BB * DD];        // outside vectors
__device__ float g_isc[TT * BB];                     // inside scores
__device__ float g_osc[TT * BB];                     // outside scores
__device__ float g_P  [(size_t)TT * BB * 3 * DD];    // [Pl | Pr | R] per cell/batch
__device__ float g_Po [(size_t)TT * BB * DD];        // ov @ W1a^T
__device__ float g_H  [(size_t)MAXM * DD];           // hidden scratch
__device__ float g_V  [(size_t)MAXM * DD];           // compose output scratch
__device__ float g_S  [MAXM];                        // scores scratch
__device__ float g_Wcat[3 * DD * DD];                // rows: W1a | W1b | W_bil

__host__ __device__ __forceinline__ int offL(int L) {
    return TT - (42 - L) * (41 - L) / 2;   // first chart index of spans of length L
}

__device__ __forceinline__ float blockReduce256(float v) {
    __shared__ float sh[8];
    int lane = threadIdx.x & 31, w = threadIdx.x >> 5;
    #pragma unroll
    for (int o = 16; o; o >>= 1) v += __shfl_down_sync(0xffffffffu, v, o);
    __syncthreads();
    if (lane == 0) sh[w] = v;
    __syncthreads();
    if (threadIdx.x == 0) {
        float s = 0.f;
        #pragma unroll
        for (int i = 0; i < 8; i++) s += sh[i];
        v = s;
    }
    __syncthreads();
    return v;   // valid in thread 0
}

// ---------------- init kernels ----------------
__global__ void k_init_sc() {
    int i = blockIdx.x * 256 + threadIdx.x;
    if (i < TT * BB) { g_isc[i] = 0.f; g_osc[i] = 0.f; }
}
__global__ void k_copy_base(const float* __restrict__ src) {
    size_t i = (size_t)blockIdx.x * 256 + threadIdx.x;
    if (i < (size_t)NN * BB * DD) g_iv[i] = src[i];
}
__global__ void k_root(const float* __restrict__ rb) {
    int i = blockIdx.x * 256 + threadIdx.x;
    if (i < BB * DD) g_ov[(size_t)offL(NN) * BB * DD + i] = rb[i % DD];
}
__global__ void k_build_wcat(const float* __restrict__ W1, const float* __restrict__ Wb) {
    int i = blockIdx.x * 256 + threadIdx.x;
    if (i >= 3 * DD * DD) return;
    int j = i / DD, k = i % DD;
    float v;
    if (j < DD)            v = W1[(size_t)j * (2 * DD) + k];            // W1a: W1[j, k]
    else if (j < 2 * DD)   v = W1[(size_t)(j - DD) * (2 * DD) + DD + k];// W1b: W1[j, D+k]
    else                   v = Wb[(size_t)(j - 2 * DD) * DD + k];       // W_bil[j, k]
    g_Wcat[i] = v;
}
__global__ void k_zero_out(float* out) { if (threadIdx.x == 0) out[0] = 0.f; }

// ---------------- tensor-core helpers ----------------
__device__ __forceinline__ uint32_t tf32hi(float x) {
    uint32_t r;
    asm("cvt.rna.tf32.f32 %0, %1;" : "=r"(r) : "f"(x));
    return r;
}
__device__ __forceinline__ void mma8(float* c, const uint32_t* a, uint32_t b0, uint32_t b1) {
    asm volatile(
        "mma.sync.aligned.m16n8k8.row.col.f32.tf32.tf32.f32 "
        "{%0,%1,%2,%3},{%4,%5,%6,%7},{%8,%9},{%0,%1,%2,%3};"
        : "+f"(c[0]), "+f"(c[1]), "+f"(c[2]), "+f"(c[3])
        : "r"(a[0]), "r"(a[1]), "r"(a[2]), "r"(a[3]), "r"(b0), "r"(b1));
}

// ---------------- tensor-core GEMM (single-pass TF32, rna rounding) --------
//  C[m,n] = act( sum_k A[m,k]*W[n,k] + bias[n] )
//  requires: K % 32 == 0, N % 128 == 0
#define KC 32
#define KPAD (KC + 4)
__global__ __launch_bounds__(256) void k_gemm_tc(
    const float* __restrict__ A, int lda,
    const float* __restrict__ W, int ldw,
    const float* __restrict__ bias,
    float* __restrict__ C, int ldc,
    int M, int N, int K, int doRelu)
{
    __shared__ float As[128][KPAD];   // [m][k]
    __shared__ float Bs[128][KPAD];   // [n][k]
    int tid = threadIdx.x;
    int warp = tid >> 5, lane = tid & 31;
    int m0 = blockIdx.y * 128, n0 = blockIdx.x * 128;
    int wm = (warp >> 2) * 64;        // warp m offset within tile
    int wn = (warp & 3) * 32;         // warp n offset within tile
    int g = lane >> 2, tg = lane & 3; // groupID, thread-in-group

    float acc[4][4][4];               // [mtile][ntile][frag]
    #pragma unroll
    for (int i = 0; i < 4; i++)
        #pragma unroll
        for (int j = 0; j < 4; j++)
            #pragma unroll
            for (int c = 0; c < 4; c++) acc[i][j][c] = 0.f;

    int lrow = tid >> 1;
    int lk = (tid & 1) * 16;
    const float* aptr = A + (size_t)(m0 + lrow) * lda + lk;
    const float* wptr = W + (size_t)(n0 + lrow) * ldw + lk;
    bool aok = (m0 + lrow) < M;

    for (int k0 = 0; k0 < K; k0 += KC) {
        #pragma unroll
        for (int i = 0; i < 4; i++) {
            float4 av = make_float4(0.f, 0.f, 0.f, 0.f);
            if (aok) av = *(const float4*)(aptr + k0 + i * 4);
            *(float4*)&As[lrow][lk + i * 4] = av;
            float4 bv = *(const float4*)(wptr + k0 + i * 4);
            *(float4*)&Bs[lrow][lk + i * 4] = bv;
        }
        __syncthreads();

        #pragma unroll
        for (int ks = 0; ks < KC; ks += 8) {
            // A fragments (tf32, round-to-nearest)
            uint32_t ahi[4][4];
            #pragma unroll
            for (int mt = 0; mt < 4; mt++) {
                int r = wm + mt * 16 + g;
                ahi[mt][0] = tf32hi(As[r][ks + tg]);
                ahi[mt][1] = tf32hi(As[r + 8][ks + tg]);
                ahi[mt][2] = tf32hi(As[r][ks + tg + 4]);
                ahi[mt][3] = tf32hi(As[r + 8][ks + tg + 4]);
            }
            #pragma unroll
            for (int nt = 0; nt < 4; nt++) {
                int c = wn + nt * 8 + g;
                uint32_t bh0 = tf32hi(Bs[c][ks + tg]);
                uint32_t bh1 = tf32hi(Bs[c][ks + tg + 4]);
                #pragma unroll
                for (int mt = 0; mt < 4; mt++)
                    mma8(acc[mt][nt], ahi[mt], bh0, bh1);
            }
        }
        __syncthreads();
    }

    // epilogue: bias + optional relu, float2 stores
    #pragma unroll
    for (int mt = 0; mt < 4; mt++) {
        int r0 = m0 + wm + mt * 16 + g;
        #pragma unroll
        for (int nt = 0; nt < 4; nt++) {
            int cc = n0 + wn + nt * 8 + tg * 2;
            float bx = bias ? bias[cc] : 0.f;
            float by = bias ? bias[cc + 1] : 0.f;
            float v0 = acc[mt][nt][0] + bx, v1 = acc[mt][nt][1] + by;
            float v2 = acc[mt][nt][2] + bx, v3 = acc[mt][nt][3] + by;
            if (doRelu) {
                v0 = fmaxf(v0, 0.f); v1 = fmaxf(v1, 0.f);
                v2 = fmaxf(v2, 0.f); v3 = fmaxf(v3, 0.f);
            }
            if (r0 < M)     *(float2*)(C + (size_t)r0 * ldc + cc)       = make_float2(v0, v1);
            if (r0 + 8 < M) *(float2*)(C + (size_t)(r0 + 8) * ldc + cc) = make_float2(v2, v3);
        }
    }
}

// ---------------- per-combo combine: H = relu(Pl+Pr+b1), S = l.W.r + isc + isc
__global__ __launch_bounds__(256) void k_comb_inside(int L, int nb, int ns,
                                                     const float* __restrict__ b1) {
    int rid = blockIdx.x;
    int batch = rid % BB;
    int t = rid / BB;
    int si = t % ns;
    int b = t / ns;
    int s = si + 1;
    int il = offL(s) + b;
    int ir = offL(L - s) + b + s;
    const float* pl  = g_P + ((size_t)il * BB + batch) * (3 * DD);
    const float* prr = g_P + ((size_t)ir * BB + batch) * (3 * DD);
    const float* xl  = g_iv + ((size_t)il * BB + batch) * DD;
    float* hrow = g_H + (size_t)rid * DD;
    float dot = 0.f;
    for (int d = threadIdx.x; d < DD; d += 256) {
        float h = pl[d] + prr[DD + d] + b1[d];
        hrow[d] = h > 0.f ? h : 0.f;
        dot += xl[d] * prr[2 * DD + d];
    }
    dot = blockReduce256(dot);
    if (threadIdx.x == 0)
        g_S[rid] = dot + g_isc[il * BB + batch] + g_isc[ir * BB + batch];
}

__global__ __launch_bounds__(256) void k_comb_outside(int L, int nb, int nso,
                                                      const float* __restrict__ b1) {
    int rid = blockIdx.x;
    int batch = rid % BB;
    int t = rid / BB;
    int k = t % nso;
    int b = t / nso;
    int ip, isx;
    if (k < b) {
        int c = k;
        ip  = offL(b + L - c) + c;   // parent span (c, b+L)
        isx = offL(b - c) + c;       // sibling (c, b)
    } else {
        int c = b + L + 1 + (k - b);
        ip  = offL(c - b) + b;       // parent span (b, c)
        isx = offL(c - b - L) + b + L; // sibling (b+L, c)
    }
    const float* pl  = g_Po + ((size_t)ip * BB + batch) * DD;
    const float* prr = g_P  + ((size_t)isx * BB + batch) * (3 * DD);
    const float* xp  = g_ov + ((size_t)ip * BB + batch) * DD;
    float* hrow = g_H + (size_t)rid * DD;
    float dot = 0.f;
    for (int d = threadIdx.x; d < DD; d += 256) {
        float h = pl[d] + prr[DD + d] + b1[d];
        hrow[d] = h > 0.f ? h : 0.f;
        dot += xp[d] * prr[2 * DD + d];
    }
    dot = blockReduce256(dot);
    if (threadIdx.x == 0)
        g_S[rid] = dot + g_osc[ip * BB + batch] + g_isc[isx * BB + batch];
}

// ---------------- softmax over splits + weighted mix into chart cell
__global__ __launch_bounds__(256) void k_smx(int ns, int cell0,
                                             const float* __restrict__ V,
                                             float* __restrict__ vout,
                                             float* __restrict__ scout) {
    int bid = blockIdx.x;
    int batch = bid % BB;
    int b = bid / BB;
    __shared__ float sv[40], wv[40];
    int base = (b * ns) * BB + batch;   // row for split s = base + s*BB
    if (threadIdx.x < ns) sv[threadIdx.x] = g_S[base + threadIdx.x * BB];
    __syncthreads();
    if (threadIdx.x == 0) {
        float mx = -1e30f;
        for (int s = 0; s < ns; s++) mx = fmaxf(mx, sv[s]);
        float Z = 0.f;
        for (int s = 0; s < ns; s++) { float e = expf(sv[s] - mx); wv[s] = e; Z += e; }
        float inv = 1.f / Z, sc = 0.f;
        for (int s = 0; s < ns; s++) { wv[s] *= inv; sc += wv[s] * sv[s]; }
        scout[(cell0 + b) * BB + batch] = sc;
    }
    __syncthreads();
    float* orow = vout + ((size_t)(cell0 + b) * BB + batch) * DD;
    for (int d = threadIdx.x; d < DD; d += 256) {
        float acc = 0.f;
        for (int s = 0; s < ns; s++)
            acc += wv[s] * V[(size_t)(base + s * BB) * DD + d];
        orow[d] = acc;
    }
}

// ---------------- final cosine loss ----------------
__global__ __launch_bounds__(256) void k_loss(const float* __restrict__ base,
                                              float* __restrict__ out) {
    int bid = blockIdx.x;
    int batch = bid % BB;
    int n = bid / BB;
    const float* tv = g_ov + ((size_t)n * BB + batch) * DD;
    const float* bv = base + ((size_t)n * BB + batch) * DD;
    float dp = 0.f, n1 = 0.f, n2 = 0.f;
    for (int d = threadIdx.x; d < DD; d += 256) {
        float a = tv[d], c = bv[d];
        dp += a * c; n1 += a * a; n2 += c * c;
    }
    dp = blockReduce256(dp);
    n1 = blockReduce256(n1);
    n2 = blockReduce256(n2);
    if (threadIdx.x == 0) {
        float den = fmaxf(sqrtf(n1) * sqrtf(n2), 1e-8f);
        atomicAdd(out, (1.f - dp / den) * (1.f / (NN * BB)));
    }
}

// ---------------- host launcher ----------------
extern "C" void kernel_launch(void* const* d_in, const int* in_sizes, int n_in,
                              void* d_out, int out_size) {
    const float* base = (const float*)d_in[0];
    const float* Wbil = (const float*)d_in[1];
    const float* W1   = (const float*)d_in[2];
    const float* b1   = (const float*)d_in[3];
    const float* W2   = (const float*)d_in[4];
    const float* b2   = (const float*)d_in[5];
    const float* rootb= (const float*)d_in[6];
    float* out = (float*)d_out;

    float *p_iv, *p_ov, *p_isc, *p_osc, *p_P, *p_Po, *p_H, *p_V, *p_Wcat;
    cudaGetSymbolAddress((void**)&p_iv,  g_iv);
    cudaGetSymbolAddress((void**)&p_ov,  g_ov);
    cudaGetSymbolAddress((void**)&p_isc, g_isc);
    cudaGetSymbolAddress((void**)&p_osc, g_osc);
    cudaGetSymbolAddress((void**)&p_P,   g_P);
    cudaGetSymbolAddress((void**)&p_Po,  g_Po);
    cudaGetSymbolAddress((void**)&p_H,   g_H);
    cudaGetSymbolAddress((void**)&p_V,   g_V);
    cudaGetSymbolAddress((void**)&p_Wcat,g_Wcat);

    k_init_sc   <<<(TT * BB + 255) / 256, 256>>>();
    k_copy_base <<<(NN * BB * DD + 255) / 256, 256>>>(base);
    k_root      <<<(BB * DD + 255) / 256, 256>>>(rootb);
    k_build_wcat<<<(3 * DD * DD + 255) / 256, 256>>>(W1, Wbil);

    // projections for base cells (cells 0..N-1)
    k_gemm_tc<<<dim3(3 * DD / 128, (NN * BB + 127) / 128), 256>>>(
        p_iv, DD, p_Wcat, DD, nullptr, p_P, 3 * DD, NN * BB, 3 * DD, DD, 0);

    // ---------------- inside pass ----------------
    for (int L = 2; L <= NN; L++) {
        int nb = NN + 1 - L, ns = L - 1;
        int M = nb * ns * BB;
        k_comb_inside<<<M, 256>>>(L, nb, ns, b1);
        k_gemm_tc<<<dim3(DD / 128, (M + 127) / 128), 256>>>(
            p_H, DD, W2, DD, b2, p_V, DD, M, DD, DD, 1);
        k_smx<<<nb * BB, 256>>>(ns, offL(L), p_V, p_iv, p_isc);
        if (L < NN) {
            size_t c0 = (size_t)offL(L);
            k_gemm_tc<<<dim3(3 * DD / 128, (nb * BB + 127) / 128), 256>>>(
                p_iv + c0 * BB * DD, DD, p_Wcat, DD, nullptr,
                p_P + c0 * BB * 3 * DD, 3 * DD, nb * BB, 3 * DD, DD, 0);
        }
    }

    // root outside projection Po = ov_root @ W1a^T
    {
        size_t c0 = (size_t)offL(NN);
        k_gemm_tc<<<dim3(DD / 128, 1), 256>>>(
            p_ov + c0 * BB * DD, DD, p_Wcat, DD, nullptr,
            p_Po + c0 * BB * DD, DD, BB, DD, DD, 0);
    }

    // ---------------- outside pass ----------------
    for (int L = NN - 1; L >= 1; L--) {
        int nb = NN + 1 - L, nso = NN - L;
        int M = nb * nso * BB;
        k_comb_outside<<<M, 256>>>(L, nb, nso, b1);
        k_gemm_tc<<<dim3(DD / 128, (M + 127) / 128), 256>>>(
            p_H, DD, W2, DD, b2, p_V, DD, M, DD, DD, 1);
        k_smx<<<nb * BB, 256>>>(nso, offL(L), p_V, p_ov, p_osc);
        if (L > 1) {
            size_t c0 = (size_t)offL(L);
            k_gemm_tc<<<dim3(DD / 128, (nb * BB + 127) / 128), 256>>>(
                p_ov + c0 * BB * DD, DD, p_Wcat, DD, nullptr,
                p_Po + c0 * BB * DD, DD, nb * BB, DD, DD, 0);
        }
    }

    k_zero_out<<<1, 1>>>(out);
    k_loss<<<NN * BB, 256>>>(base, out);
}

// round 6
// speedup vs baseline: 3.3962x; 1.5894x over previous
#include <cuda_runtime.h>
#include <cuda_bf16.h>
#include <math.h>
#include <stdint.h>

#define NN 40
#define BB 32
#define DD 768
#define TT 820
#define MAXM 49920   // outside L=1: 40*39*32 combos

typedef __nv_bfloat16 bf16;
typedef __nv_bfloat162 bf162;

// ---------------- static scratch (no allocations allowed) ----------------
__device__ float g_iv [(size_t)TT * BB * DD];        // inside vectors (fp32)
__device__ float g_ov [(size_t)TT * BB * DD];        // outside vectors (fp32)
__device__ float g_isc[TT * BB];                     // inside scores
__device__ float g_osc[TT * BB];                     // outside scores
__device__ float g_P  [(size_t)TT * BB * 3 * DD];    // [Pl | Pr | R] per cell/batch (fp32)
__device__ float g_Po [(size_t)TT * BB * DD];        // ov @ W1a^T (fp32)
__device__ bf16  g_Hb [(size_t)MAXM * DD];           // hidden scratch (bf16)
__device__ float g_V  [(size_t)MAXM * DD];           // compose output scratch
__device__ float g_S  [MAXM];                        // scores scratch
__device__ bf16  g_Wcatb[3 * DD * DD];               // bf16 rows: W1a | W1b | W_bil
__device__ bf16  g_W2b  [DD * DD];                   // bf16 W2

__host__ __device__ __forceinline__ int offL(int L) {
    return TT - (42 - L) * (41 - L) / 2;   // first chart index of spans of length L
}

__device__ __forceinline__ float blockReduce256(float v) {
    __shared__ float sh[8];
    int lane = threadIdx.x & 31, w = threadIdx.x >> 5;
    #pragma unroll
    for (int o = 16; o; o >>= 1) v += __shfl_down_sync(0xffffffffu, v, o);
    __syncthreads();
    if (lane == 0) sh[w] = v;
    __syncthreads();
    if (threadIdx.x == 0) {
        float s = 0.f;
        #pragma unroll
        for (int i = 0; i < 8; i++) s += sh[i];
        v = s;
    }
    __syncthreads();
    return v;   // valid in thread 0
}

// ---------------- init kernels ----------------
__global__ void k_init_sc() {
    int i = blockIdx.x * 256 + threadIdx.x;
    if (i < TT * BB) { g_isc[i] = 0.f; g_osc[i] = 0.f; }
}
__global__ void k_copy_base(const float* __restrict__ src) {
    size_t i = (size_t)blockIdx.x * 256 + threadIdx.x;
    if (i < (size_t)NN * BB * DD) g_iv[i] = src[i];
}
__global__ void k_root(const float* __restrict__ rb) {
    int i = blockIdx.x * 256 + threadIdx.x;
    if (i < BB * DD) g_ov[(size_t)offL(NN) * BB * DD + i] = rb[i % DD];
}
__global__ void k_build_wcat(const float* __restrict__ W1, const float* __restrict__ Wb) {
    int i = blockIdx.x * 256 + threadIdx.x;
    if (i >= 3 * DD * DD) return;
    int j = i / DD, k = i % DD;
    float v;
    if (j < DD)            v = W1[(size_t)j * (2 * DD) + k];            // W1a: W1[j, k]
    else if (j < 2 * DD)   v = W1[(size_t)(j - DD) * (2 * DD) + DD + k];// W1b: W1[j, D+k]
    else                   v = Wb[(size_t)(j - 2 * DD) * DD + k];       // W_bil[j, k]
    g_Wcatb[i] = __float2bfloat16(v);
}
__global__ void k_conv_w2(const float* __restrict__ W2) {
    int i = blockIdx.x * 256 + threadIdx.x;
    if (i < DD * DD) g_W2b[i] = __float2bfloat16(W2[i]);
}
__global__ void k_zero_out(float* out) { if (threadIdx.x == 0) out[0] = 0.f; }

// ---------------- bf16 tensor-core mma ----------------
__device__ __forceinline__ void mma16(float* c, const uint32_t* a, uint32_t b0, uint32_t b1) {
    asm volatile(
        "mma.sync.aligned.m16n8k16.row.col.f32.bf16.bf16.f32 "
        "{%0,%1,%2,%3},{%4,%5,%6,%7},{%8,%9},{%0,%1,%2,%3};"
        : "+f"(c[0]), "+f"(c[1]), "+f"(c[2]), "+f"(c[3])
        : "r"(a[0]), "r"(a[1]), "r"(a[2]), "r"(a[3]), "r"(b0), "r"(b1));
}

// ---------------- bf16 tensor-core GEMM ----------------
//  C[m,n] = act( sum_k A[m,k]*W[n,k] + bias[n] ),  W in bf16
//  AFP32=1: A is fp32 (converted on smem store);  AFP32=0: A is bf16
//  requires: K % 64 == 0, N % 128 == 0
#define KC 64
#define KPAD 72
template<int AFP32>
__global__ __launch_bounds__(256) void k_gemm_bf(
    const void* __restrict__ Avoid, int lda,
    const bf16* __restrict__ W, int ldw,
    const float* __restrict__ bias,
    float* __restrict__ C, int ldc,
    int M, int N, int K, int doRelu)
{
    __shared__ bf16 As[128][KPAD];   // [m][k]
    __shared__ bf16 Bs[128][KPAD];   // [n][k]
    int tid = threadIdx.x;
    int warp = tid >> 5, lane = tid & 31;
    int m0 = blockIdx.y * 128, n0 = blockIdx.x * 128;
    int wm = (warp >> 2) * 64;        // warp m offset within tile
    int wn = (warp & 3) * 32;         // warp n offset within tile
    int g = lane >> 2, tg = lane & 3; // groupID, thread-in-group

    float acc[4][4][4];               // [mtile][ntile][frag]
    #pragma unroll
    for (int i = 0; i < 4; i++)
        #pragma unroll
        for (int j = 0; j < 4; j++)
            #pragma unroll
            for (int c = 0; c < 4; c++) acc[i][j][c] = 0.f;

    int lrow = tid >> 1;              // 0..127
    int lk = (tid & 1) * 32;          // 0 or 32
    const float* aptrF = (const float*)Avoid + (size_t)(m0 + lrow) * lda + lk;
    const bf16*  aptrB = (const bf16*) Avoid + (size_t)(m0 + lrow) * lda + lk;
    const bf16*  wptr  = W + (size_t)(n0 + lrow) * ldw + lk;
    bool aok = (m0 + lrow) < M;

    for (int k0 = 0; k0 < K; k0 += KC) {
        if (AFP32) {
            #pragma unroll
            for (int i = 0; i < 8; i++) {
                float4 v = make_float4(0.f, 0.f, 0.f, 0.f);
                if (aok) v = *(const float4*)(aptrF + k0 + i * 4);
                *(bf162*)&As[lrow][lk + i * 4]     = __floats2bfloat162_rn(v.x, v.y);
                *(bf162*)&As[lrow][lk + i * 4 + 2] = __floats2bfloat162_rn(v.z, v.w);
            }
        } else {
            #pragma unroll
            for (int i = 0; i < 4; i++) {
                uint4 v = make_uint4(0u, 0u, 0u, 0u);
                if (aok) v = *(const uint4*)(aptrB + k0 + i * 8);
                *(uint4*)&As[lrow][lk + i * 8] = v;
            }
        }
        #pragma unroll
        for (int i = 0; i < 4; i++) {
            uint4 v = *(const uint4*)(wptr + k0 + i * 8);
            *(uint4*)&Bs[lrow][lk + i * 8] = v;
        }
        __syncthreads();

        #pragma unroll
        for (int ks = 0; ks < KC; ks += 16) {
            uint32_t a[4][4];
            #pragma unroll
            for (int mt = 0; mt < 4; mt++) {
                int r = wm + mt * 16 + g;
                a[mt][0] = *(const uint32_t*)&As[r][ks + 2 * tg];
                a[mt][1] = *(const uint32_t*)&As[r + 8][ks + 2 * tg];
                a[mt][2] = *(const uint32_t*)&As[r][ks + 2 * tg + 8];
                a[mt][3] = *(const uint32_t*)&As[r + 8][ks + 2 * tg + 8];
            }
            #pragma unroll
            for (int nt = 0; nt < 4; nt++) {
                int c = wn + nt * 8 + g;
                uint32_t b0 = *(const uint32_t*)&Bs[c][ks + 2 * tg];
                uint32_t b1 = *(const uint32_t*)&Bs[c][ks + 2 * tg + 8];
                #pragma unroll
                for (int mt = 0; mt < 4; mt++)
                    mma16(acc[mt][nt], a[mt], b0, b1);
            }
        }
        __syncthreads();
    }

    // epilogue: bias + optional relu, float2 stores
    #pragma unroll
    for (int mt = 0; mt < 4; mt++) {
        int r0 = m0 + wm + mt * 16 + g;
        #pragma unroll
        for (int nt = 0; nt < 4; nt++) {
            int cc = n0 + wn + nt * 8 + tg * 2;
            float bx = bias ? bias[cc] : 0.f;
            float by = bias ? bias[cc + 1] : 0.f;
            float v0 = acc[mt][nt][0] + bx, v1 = acc[mt][nt][1] + by;
            float v2 = acc[mt][nt][2] + bx, v3 = acc[mt][nt][3] + by;
            if (doRelu) {
                v0 = fmaxf(v0, 0.f); v1 = fmaxf(v1, 0.f);
                v2 = fmaxf(v2, 0.f); v3 = fmaxf(v3, 0.f);
            }
            if (r0 < M)     *(float2*)(C + (size_t)r0 * ldc + cc)       = make_float2(v0, v1);
            if (r0 + 8 < M) *(float2*)(C + (size_t)(r0 + 8) * ldc + cc) = make_float2(v2, v3);
        }
    }
}

// ---------------- per-combo combine: Hb = bf16(relu(Pl+Pr+b1)), S = l.W.r + scores
__global__ __launch_bounds__(256) void k_comb_inside(int L, int nb, int ns,
                                                     const float* __restrict__ b1) {
    int rid = blockIdx.x;
    int batch = rid % BB;
    int t = rid / BB;
    int si = t % ns;
    int b = t / ns;
    int s = si + 1;
    int il = offL(s) + b;
    int ir = offL(L - s) + b + s;
    const float* pl  = g_P + ((size_t)il * BB + batch) * (3 * DD);
    const float* prr = g_P + ((size_t)ir * BB + batch) * (3 * DD);
    const float* xl  = g_iv + ((size_t)il * BB + batch) * DD;
    bf16* hrow = g_Hb + (size_t)rid * DD;
    float dot = 0.f;
    for (int d = threadIdx.x; d < DD; d += 256) {
        float h = pl[d] + prr[DD + d] + b1[d];
        hrow[d] = __float2bfloat16(h > 0.f ? h : 0.f);
        dot += xl[d] * prr[2 * DD + d];
    }
    dot = blockReduce256(dot);
    if (threadIdx.x == 0)
        g_S[rid] = dot + g_isc[il * BB + batch] + g_isc[ir * BB + batch];
}

__global__ __launch_bounds__(256) void k_comb_outside(int L, int nb, int nso,
                                                      const float* __restrict__ b1) {
    int rid = blockIdx.x;
    int batch = rid % BB;
    int t = rid / BB;
    int k = t % nso;
    int b = t / nso;
    int ip, isx;
    if (k < b) {
        int c = k;
        ip  = offL(b + L - c) + c;   // parent span (c, b+L)
        isx = offL(b - c) + c;       // sibling (c, b)
    } else {
        int c = b + L + 1 + (k - b);
        ip  = offL(c - b) + b;       // parent span (b, c)
        isx = offL(c - b - L) + b + L; // sibling (b+L, c)
    }
    const float* pl  = g_Po + ((size_t)ip * BB + batch) * DD;
    const float* prr = g_P  + ((size_t)isx * BB + batch) * (3 * DD);
    const float* xp  = g_ov + ((size_t)ip * BB + batch) * DD;
    bf16* hrow = g_Hb + (size_t)rid * DD;
    float dot = 0.f;
    for (int d = threadIdx.x; d < DD; d += 256) {
        float h = pl[d] + prr[DD + d] + b1[d];
        hrow[d] = __float2bfloat16(h > 0.f ? h : 0.f);
        dot += xp[d] * prr[2 * DD + d];
    }
    dot = blockReduce256(dot);
    if (threadIdx.x == 0)
        g_S[rid] = dot + g_osc[ip * BB + batch] + g_isc[isx * BB + batch];
}

// ---------------- softmax over splits + weighted mix into chart cell
__global__ __launch_bounds__(256) void k_smx(int ns, int cell0,
                                             const float* __restrict__ V,
                                             float* __restrict__ vout,
                                             float* __restrict__ scout) {
    int bid = blockIdx.x;
    int batch = bid % BB;
    int b = bid / BB;
    __shared__ float sv[40], wv[40];
    int base = (b * ns) * BB + batch;   // row for split s = base + s*BB
    if (threadIdx.x < ns) sv[threadIdx.x] = g_S[base + threadIdx.x * BB];
    __syncthreads();
    if (threadIdx.x == 0) {
        float mx = -1e30f;
        for (int s = 0; s < ns; s++) mx = fmaxf(mx, sv[s]);
        float Z = 0.f;
        for (int s = 0; s < ns; s++) { float e = expf(sv[s] - mx); wv[s] = e; Z += e; }
        float inv = 1.f / Z, sc = 0.f;
        for (int s = 0; s < ns; s++) { wv[s] *= inv; sc += wv[s] * sv[s]; }
        scout[(cell0 + b) * BB + batch] = sc;
    }
    __syncthreads();
    float* orow = vout + ((size_t)(cell0 + b) * BB + batch) * DD;
    for (int d = threadIdx.x; d < DD; d += 256) {
        float acc = 0.f;
        for (int s = 0; s < ns; s++)
            acc += wv[s] * V[(size_t)(base + s * BB) * DD + d];
        orow[d] = acc;
    }
}

// ---------------- final cosine loss ----------------
__global__ __launch_bounds__(256) void k_loss(const float* __restrict__ base,
                                              float* __restrict__ out) {
    int bid = blockIdx.x;
    int batch = bid % BB;
    int n = bid / BB;
    const float* tv = g_ov + ((size_t)n * BB + batch) * DD;
    const float* bv = base + ((size_t)n * BB + batch) * DD;
    float dp = 0.f, n1 = 0.f, n2 = 0.f;
    for (int d = threadIdx.x; d < DD; d += 256) {
        float a = tv[d], c = bv[d];
        dp += a * c; n1 += a * a; n2 += c * c;
    }
    dp = blockReduce256(dp);
    n1 = blockReduce256(n1);
    n2 = blockReduce256(n2);
    if (threadIdx.x == 0) {
        float den = fmaxf(sqrtf(n1) * sqrtf(n2), 1e-8f);
        atomicAdd(out, (1.f - dp / den) * (1.f / (NN * BB)));
    }
}

// ---------------- host launcher ----------------
extern "C" void kernel_launch(void* const* d_in, const int* in_sizes, int n_in,
                              void* d_out, int out_size) {
    const float* base = (const float*)d_in[0];
    const float* Wbil = (const float*)d_in[1];
    const float* W1   = (const float*)d_in[2];
    const float* b1   = (const float*)d_in[3];
    const float* W2   = (const float*)d_in[4];
    const float* b2   = (const float*)d_in[5];
    const float* rootb= (const float*)d_in[6];
    float* out = (float*)d_out;

    float *p_iv, *p_ov, *p_P, *p_Po, *p_V;
    bf16 *p_Hb, *p_Wcatb, *p_W2b;
    cudaGetSymbolAddress((void**)&p_iv,  g_iv);
    cudaGetSymbolAddress((void**)&p_ov,  g_ov);
    cudaGetSymbolAddress((void**)&p_P,   g_P);
    cudaGetSymbolAddress((void**)&p_Po,  g_Po);
    cudaGetSymbolAddress((void**)&p_Hb,  g_Hb);
    cudaGetSymbolAddress((void**)&p_V,   g_V);
    cudaGetSymbolAddress((void**)&p_Wcatb, g_Wcatb);
    cudaGetSymbolAddress((void**)&p_W2b,   g_W2b);
    float *p_isc, *p_osc;
    cudaGetSymbolAddress((void**)&p_isc, g_isc);
    cudaGetSymbolAddress((void**)&p_osc, g_osc);

    k_init_sc   <<<(TT * BB + 255) / 256, 256>>>();
    k_copy_base <<<(NN * BB * DD + 255) / 256, 256>>>(base);
    k_root      <<<(BB * DD + 255) / 256, 256>>>(rootb);
    k_build_wcat<<<(3 * DD * DD + 255) / 256, 256>>>(W1, Wbil);
    k_conv_w2   <<<(DD * DD + 255) / 256, 256>>>(W2);

    // projections for base cells (cells 0..N-1)
    k_gemm_bf<1><<<dim3(3 * DD / 128, (NN * BB + 127) / 128), 256>>>(
        p_iv, DD, p_Wcatb, DD, nullptr, p_P, 3 * DD, NN * BB, 3 * DD, DD, 0);

    // ---------------- inside pass ----------------
    for (int L = 2; L <= NN; L++) {
        int nb = NN + 1 - L, ns = L - 1;
        int M = nb * ns * BB;
        k_comb_inside<<<M, 256>>>(L, nb, ns, b1);
        k_gemm_bf<0><<<dim3(DD / 128, (M + 127) / 128), 256>>>(
            p_Hb, DD, p_W2b, DD, b2, p_V, DD, M, DD, DD, 1);
        k_smx<<<nb * BB, 256>>>(ns, offL(L), p_V, p_iv, p_isc);
        if (L < NN) {
            size_t c0 = (size_t)offL(L);
            k_gemm_bf<1><<<dim3(3 * DD / 128, (nb * BB + 127) / 128), 256>>>(
                p_iv + c0 * BB * DD, DD, p_Wcatb, DD, nullptr,
                p_P + c0 * BB * 3 * DD, 3 * DD, nb * BB, 3 * DD, DD, 0);
        }
    }

    // root outside projection Po = ov_root @ W1a^T  (Wcat first DD rows = W1a)
    {
        size_t c0 = (size_t)offL(NN);
        k_gemm_bf<1><<<dim3(DD / 128, 1), 256>>>(
            p_ov + c0 * BB * DD, DD, p_Wcatb, DD, nullptr,
            p_Po + c0 * BB * DD, DD, BB, DD, DD, 0);
    }

    // ---------------- outside pass ----------------
    for (int L = NN - 1; L >= 1; L--) {
        int nb = NN + 1 - L, nso = NN - L;
        int M = nb * nso * BB;
        k_comb_outside<<<M, 256>>>(L, nb, nso, b1);
        k_gemm_bf<0><<<dim3(DD / 128, (M + 127) / 128), 256>>>(
            p_Hb, DD, p_W2b, DD, b2, p_V, DD, M, DD, DD, 1);
        k_smx<<<nb * BB, 256>>>(nso, offL(L), p_V, p_ov, p_osc);
        if (L > 1) {
            size_t c0 = (size_t)offL(L);
            k_gemm_bf<1><<<dim3(DD / 128, (nb * BB + 127) / 128), 256>>>(
                p_ov + c0 * BB * DD, DD, p_Wcatb, DD, nullptr,
                p_Po + c0 * BB * DD, DD, nb * BB, DD, DD, 0);
        }
    }

    k_zero_out<<<1, 1>>>(out);
    k_loss<<<NN * BB, 256>>>(base, out);
}

// round 8
// speedup vs baseline: 4.3982x; 1.2950x over previous
#include <cuda_runtime.h>
#include <cuda_bf16.h>
#include <math.h>
#include <stdint.h>

#define NN 40
#define BB 32
#define DD 768
#define TT 820
#define MAXM 49920   // outside L=1: 40*39*32 combos

typedef __nv_bfloat16 bf16;
typedef __nv_bfloat162 bf162;

// ---------------- static scratch (no allocations allowed) ----------------
__device__ float g_iv [(size_t)TT * BB * DD];        // inside vectors (fp32)
__device__ float g_ov [(size_t)TT * BB * DD];        // outside vectors (fp32)
__device__ float g_isc[TT * BB];                     // inside scores
__device__ float g_osc[TT * BB];                     // outside scores
__device__ float g_P  [(size_t)TT * BB * 3 * DD];    // [Pl | Pr | R] per cell/batch (fp32)
__device__ float g_Po [(size_t)TT * BB * DD];        // ov @ W1a^T (fp32)
__device__ bf16  g_Hb [(size_t)MAXM * DD];           // hidden scratch (bf16)
__device__ float g_V  [(size_t)MAXM * DD];           // compose output scratch
__device__ float g_S  [MAXM];                        // scores scratch
__device__ bf16  g_Wcatb[3 * DD * DD];               // bf16 rows: W1a | W1b | W_bil
__device__ bf16  g_W2b  [DD * DD];                   // bf16 W2

__host__ __device__ __forceinline__ int offL(int L) {
    return TT - (42 - L) * (41 - L) / 2;   // first chart index of spans of length L
}

__device__ __forceinline__ float blockReduce256(float v) {
    __shared__ float sh[8];
    int lane = threadIdx.x & 31, w = threadIdx.x >> 5;
    #pragma unroll
    for (int o = 16; o; o >>= 1) v += __shfl_down_sync(0xffffffffu, v, o);
    __syncthreads();
    if (lane == 0) sh[w] = v;
    __syncthreads();
    if (threadIdx.x == 0) {
        float s = 0.f;
        #pragma unroll
        for (int i = 0; i < 8; i++) s += sh[i];
        v = s;
    }
    __syncthreads();
    return v;
}

// ---------------- init kernels ----------------
__global__ void k_init_sc() {
    int i = blockIdx.x * 256 + threadIdx.x;
    if (i < TT * BB) { g_isc[i] = 0.f; g_osc[i] = 0.f; }
}
__global__ void k_copy_base(const float* __restrict__ src) {
    size_t i = (size_t)blockIdx.x * 256 + threadIdx.x;
    if (i < (size_t)NN * BB * DD) g_iv[i] = src[i];
}
__global__ void k_root(const float* __restrict__ rb) {
    int i = blockIdx.x * 256 + threadIdx.x;
    if (i < BB * DD) g_ov[(size_t)offL(NN) * BB * DD + i] = rb[i % DD];
}
__global__ void k_build_wcat(const float* __restrict__ W1, const float* __restrict__ Wb) {
    int i = blockIdx.x * 256 + threadIdx.x;
    if (i >= 3 * DD * DD) return;
    int j = i / DD, k = i % DD;
    float v;
    if (j < DD)            v = W1[(size_t)j * (2 * DD) + k];
    else if (j < 2 * DD)   v = W1[(size_t)(j - DD) * (2 * DD) + DD + k];
    else                   v = Wb[(size_t)(j - 2 * DD) * DD + k];
    g_Wcatb[i] = __float2bfloat16(v);
}
__global__ void k_conv_w2(const float* __restrict__ W2) {
    int i = blockIdx.x * 256 + threadIdx.x;
    if (i < DD * DD) g_W2b[i] = __float2bfloat16(W2[i]);
}
__global__ void k_zero_out(float* out) { if (threadIdx.x == 0) out[0] = 0.f; }

// ---------------- tensor-core helpers ----------------
__device__ __forceinline__ void mma16(float* c, const uint32_t* a, uint32_t b0, uint32_t b1) {
    asm volatile(
        "mma.sync.aligned.m16n8k16.row.col.f32.bf16.bf16.f32 "
        "{%0,%1,%2,%3},{%4,%5,%6,%7},{%8,%9},{%0,%1,%2,%3};"
        : "+f"(c[0]), "+f"(c[1]), "+f"(c[2]), "+f"(c[3])
        : "r"(a[0]), "r"(a[1]), "r"(a[2]), "r"(a[3]), "r"(b0), "r"(b1));
}
__device__ __forceinline__ void ldsm4(uint32_t* r, const bf16* p) {
    uint32_t a = (uint32_t)__cvta_generic_to_shared(p);
    asm volatile("ldmatrix.sync.aligned.m8n8.x4.shared.b16 {%0,%1,%2,%3}, [%4];"
        : "=r"(r[0]), "=r"(r[1]), "=r"(r[2]), "=r"(r[3]) : "r"(a));
}

// ---------------- bf16 GEMM v2: cp.async double-buffered + ldmatrix --------
//  C[m,n] = act( sum_k A[m,k]*W[n,k] + bias[n] ),  W bf16
//  AFP32=1: A fp32 (sync convert);  AFP32=0: A bf16 (cp.async)
//  requires: K % 64 == 0, N % 128 == 0
//  dynamic smem: 2 stages x (A 128x64 + B 128x64) bf16 = 65536 B
//  smem layout: row r, 16B-chunk c (0..7) stored at chunk (c ^ (r&7))
#define KC 64
template<int AFP32>
__global__ __launch_bounds__(256) void k_gemm2(
    const void* __restrict__ Avoid, int lda,
    const bf16* __restrict__ W, int ldw,
    const float* __restrict__ bias,
    float* __restrict__ C, int ldc,
    int M, int N, int K, int doRelu)
{
    extern __shared__ bf16 sm[];
    const int tid = threadIdx.x;
    const int warp = tid >> 5, lane = tid & 31;
    const int m0 = blockIdx.y * 128, n0 = blockIdx.x * 128;
    const int wm = (warp >> 2) * 64, wn = (warp & 3) * 32;
    const int g = lane >> 2, tg = lane & 3;

    float acc[4][4][4];
    #pragma unroll
    for (int i = 0; i < 4; i++)
        #pragma unroll
        for (int j = 0; j < 4; j++)
            #pragma unroll
            for (int c = 0; c < 4; c++) acc[i][j][c] = 0.f;

    // loader indices: row = tid>>1 (0..127), chunks cbase..cbase+3
    const int lrow = tid >> 1;
    const int cbase = (tid & 1) * 4;
    const int lsw = lrow & 7;
    const float* aF = (const float*)Avoid;
    const bf16*  aB = (const bf16*)Avoid;
    const int arow = m0 + lrow;
    const bool aok = arow < M;
    const int arc = aok ? arow : 0;

    // fragment lane geometry (constant across k)
    const int ra = (lane & 7) + (lane & 8);        // A row offset in 16-group
    const int ca = (lane >> 4) & 1;                // A chunk offset
    const int nboff = (lane & 7) + ((lane >> 4) & 1) * 8;  // B n offset in 16-group
    const int cb = (lane >> 3) & 1;                // B chunk offset
    const int fsw = lane & 7;                      // swizzle key for fragments

    const int nk = K / KC;

    auto issue = [&](int kc) {
        int k0 = kc * KC;
        bf16* As = sm + (kc & 1) * 16384;
        bf16* Bs = As + 8192;
        if (AFP32) {
            #pragma unroll
            for (int j = 0; j < 4; j++) {
                int c = cbase + j;
                float4 v0 = make_float4(0.f,0.f,0.f,0.f), v1 = v0;
                if (aok) {
                    const float* s = aF + (size_t)arow * lda + k0 + c * 8;
                    v0 = *(const float4*)s;
                    v1 = *(const float4*)(s + 4);
                }
                bf162* d = (bf162*)(As + lrow * 64 + ((c ^ lsw) * 8));
                d[0] = __floats2bfloat162_rn(v0.x, v0.y);
                d[1] = __floats2bfloat162_rn(v0.z, v0.w);
                d[2] = __floats2bfloat162_rn(v1.x, v1.y);
                d[3] = __floats2bfloat162_rn(v1.z, v1.w);
            }
        } else {
            #pragma unroll
            for (int j = 0; j < 4; j++) {
                int c = cbase + j;
                const bf16* s = aB + (size_t)arc * lda + k0 + c * 8;
                uint32_t d = (uint32_t)__cvta_generic_to_shared(As + lrow * 64 + ((c ^ lsw) * 8));
                int sz = aok ? 16 : 0;
                asm volatile("cp.async.cg.shared.global [%0], [%1], 16, %2;"
                             :: "r"(d), "l"(s), "r"(sz));
            }
        }
        #pragma unroll
        for (int j = 0; j < 4; j++) {
            int c = cbase + j;
            const bf16* s = W + (size_t)(n0 + lrow) * ldw + k0 + c * 8;
            uint32_t d = (uint32_t)__cvta_generic_to_shared(Bs + lrow * 64 + ((c ^ lsw) * 8));
            asm volatile("cp.async.cg.shared.global [%0], [%1], 16, 16;"
                         :: "r"(d), "l"(s));
        }
        asm volatile("cp.async.commit_group;");
    };

    issue(0);
    for (int kc = 0; kc < nk; kc++) {
        if (kc + 1 < nk) {
            issue(kc + 1);
            asm volatile("cp.async.wait_group 1;");
        } else {
            asm volatile("cp.async.wait_group 0;");
        }
        __syncthreads();
        const bf16* As = sm + (kc & 1) * 16384;
        const bf16* Bs = As + 8192;
        #pragma unroll
        for (int ks = 0; ks < 4; ks++) {
            int c0 = ks * 2;
            uint32_t a[4][4];
            #pragma unroll
            for (int mt = 0; mt < 4; mt++)
                ldsm4(a[mt], As + (wm + mt * 16 + ra) * 64 + (((c0 + ca) ^ fsw) * 8));
            uint32_t q[2][4];
            #pragma unroll
            for (int ntp = 0; ntp < 2; ntp++)
                ldsm4(q[ntp], Bs + (wn + ntp * 16 + nboff) * 64 + (((c0 + cb) ^ fsw) * 8));
            #pragma unroll
            for (int ntp = 0; ntp < 2; ntp++)
                #pragma unroll
                for (int h = 0; h < 2; h++)
                    #pragma unroll
                    for (int mt = 0; mt < 4; mt++)
                        mma16(acc[mt][ntp * 2 + h], a[mt], q[ntp][h * 2], q[ntp][h * 2 + 1]);
        }
        __syncthreads();
    }

    // epilogue: bias + optional relu
    #pragma unroll
    for (int mt = 0; mt < 4; mt++) {
        int r0 = m0 + wm + mt * 16 + g;
        #pragma unroll
        for (int nt = 0; nt < 4; nt++) {
            int cc = n0 + wn + nt * 8 + tg * 2;
            float bx = bias ? bias[cc] : 0.f;
            float by = bias ? bias[cc + 1] : 0.f;
            float v0 = acc[mt][nt][0] + bx, v1 = acc[mt][nt][1] + by;
            float v2 = acc[mt][nt][2] + bx, v3 = acc[mt][nt][3] + by;
            if (doRelu) {
                v0 = fmaxf(v0, 0.f); v1 = fmaxf(v1, 0.f);
                v2 = fmaxf(v2, 0.f); v3 = fmaxf(v3, 0.f);
            }
            if (r0 < M)     *(float2*)(C + (size_t)r0 * ldc + cc)       = make_float2(v0, v1);
            if (r0 + 8 < M) *(float2*)(C + (size_t)(r0 + 8) * ldc + cc) = make_float2(v2, v3);
        }
    }
}

// ---------------- per-combo combine (warp-per-row) ----------------
__global__ __launch_bounds__(256) void k_comb_inside(int L, int ns, int M,
                                                     const float* __restrict__ b1) {
    int w = threadIdx.x >> 5, lane = threadIdx.x & 31;
    int rid = blockIdx.x * 8 + w;
    if (rid >= M) return;
    int batch = rid % BB;
    int t = rid / BB;
    int si = t % ns, b = t / ns;
    int s = si + 1;
    int il = offL(s) + b;
    int ir = offL(L - s) + b + s;
    const float4* pl = (const float4*)(g_P + ((size_t)il * BB + batch) * 3 * DD);
    const float4* pr = (const float4*)(g_P + ((size_t)ir * BB + batch) * 3 * DD);
    const float4* xl = (const float4*)(g_iv + ((size_t)il * BB + batch) * DD);
    const float4* b14 = (const float4*)b1;
    bf162* hrow = (bf162*)(g_Hb + (size_t)rid * DD);
    float dot = 0.f;
    #pragma unroll
    for (int i = 0; i < 6; i++) {
        int e = lane + 32 * i;
        float4 a  = pl[e];
        float4 bb = pr[DD / 4 + e];
        float4 r  = pr[2 * (DD / 4) + e];
        float4 x  = xl[e];
        float4 bv = b14[e];
        float h0 = fmaxf(a.x + bb.x + bv.x, 0.f);
        float h1 = fmaxf(a.y + bb.y + bv.y, 0.f);
        float h2 = fmaxf(a.z + bb.z + bv.z, 0.f);
        float h3 = fmaxf(a.w + bb.w + bv.w, 0.f);
        hrow[2 * e]     = __floats2bfloat162_rn(h0, h1);
        hrow[2 * e + 1] = __floats2bfloat162_rn(h2, h3);
        dot += x.x * r.x + x.y * r.y + x.z * r.z + x.w * r.w;
    }
    #pragma unroll
    for (int o = 16; o; o >>= 1) dot += __shfl_down_sync(0xffffffffu, dot, o);
    if (lane == 0)
        g_S[rid] = dot + g_isc[il * BB + batch] + g_isc[ir * BB + batch];
}

__global__ __launch_bounds__(256) void k_comb_outside(int L, int nso, int M,
                                                      const float* __restrict__ b1) {
    int w = threadIdx.x >> 5, lane = threadIdx.x & 31;
    int rid = blockIdx.x * 8 + w;
    if (rid >= M) return;
    int batch = rid % BB;
    int t = rid / BB;
    int k = t % nso, b = t / nso;
    int ip, isx;
    if (k < b) {
        int c = k;
        ip  = offL(b + L - c) + c;
        isx = offL(b - c) + c;
    } else {
        int c = b + L + 1 + (k - b);
        ip  = offL(c - b) + b;
        isx = offL(c - b - L) + b + L;
    }
    const float4* pl = (const float4*)(g_Po + ((size_t)ip * BB + batch) * DD);
    const float4* pr = (const float4*)(g_P + ((size_t)isx * BB + batch) * 3 * DD);
    const float4* xp = (const float4*)(g_ov + ((size_t)ip * BB + batch) * DD);
    const float4* b14 = (const float4*)b1;
    bf162* hrow = (bf162*)(g_Hb + (size_t)rid * DD);
    float dot = 0.f;
    #pragma unroll
    for (int i = 0; i < 6; i++) {
        int e = lane + 32 * i;
        float4 a  = pl[e];
        float4 bb = pr[DD / 4 + e];
        float4 r  = pr[2 * (DD / 4) + e];
        float4 x  = xp[e];
        float4 bv = b14[e];
        float h0 = fmaxf(a.x + bb.x + bv.x, 0.f);
        float h1 = fmaxf(a.y + bb.y + bv.y, 0.f);
        float h2 = fmaxf(a.z + bb.z + bv.z, 0.f);
        float h3 = fmaxf(a.w + bb.w + bv.w, 0.f);
        hrow[2 * e]     = __floats2bfloat162_rn(h0, h1);
        hrow[2 * e + 1] = __floats2bfloat162_rn(h2, h3);
        dot += x.x * r.x + x.y * r.y + x.z * r.z + x.w * r.w;
    }
    #pragma unroll
    for (int o = 16; o; o >>= 1) dot += __shfl_down_sync(0xffffffffu, dot, o);
    if (lane == 0)
        g_S[rid] = dot + g_osc[ip * BB + batch] + g_isc[isx * BB + batch];
}

// ---------------- softmax over splits + weighted mix into chart cell
__global__ __launch_bounds__(256) void k_smx(int ns, int cell0,
                                             const float* __restrict__ V,
                                             float* __restrict__ vout,
                                             float* __restrict__ scout) {
    int bid = blockIdx.x;
    int batch = bid % BB;
    int b = bid / BB;
    __shared__ float sv[40], wv[40];
    int base = (b * ns) * BB + batch;
    if (threadIdx.x < ns) sv[threadIdx.x] = g_S[base + threadIdx.x * BB];
    __syncthreads();
    if (threadIdx.x == 0) {
        float mx = -1e30f;
        for (int s = 0; s < ns; s++) mx = fmaxf(mx, sv[s]);
        float Z = 0.f;
        for (int s = 0; s < ns; s++) { float e = expf(sv[s] - mx); wv[s] = e; Z += e; }
        float inv = 1.f / Z, sc = 0.f;
        for (int s = 0; s < ns; s++) { wv[s] *= inv; sc += wv[s] * sv[s]; }
        scout[(cell0 + b) * BB + batch] = sc;
    }
    __syncthreads();
    float* orow = vout + ((size_t)(cell0 + b) * BB + batch) * DD;
    for (int d = threadIdx.x; d < DD; d += 256) {
        float acc = 0.f;
        for (int s = 0; s < ns; s++)
            acc += wv[s] * V[(size_t)(base + s * BB) * DD + d];
        orow[d] = acc;
    }
}

// ---------------- final cosine loss ----------------
__global__ __launch_bounds__(256) void k_loss(const float* __restrict__ base,
                                              float* __restrict__ out) {
    int bid = blockIdx.x;
    int batch = bid % BB;
    int n = bid / BB;
    const float* tv = g_ov + ((size_t)n * BB + batch) * DD;
    const float* bv = base + ((size_t)n * BB + batch) * DD;
    float dp = 0.f, n1 = 0.f, n2 = 0.f;
    for (int d = threadIdx.x; d < DD; d += 256) {
        float a = tv[d], c = bv[d];
        dp += a * c; n1 += a * a; n2 += c * c;
    }
    dp = blockReduce256(dp);
    n1 = blockReduce256(n1);
    n2 = blockReduce256(n2);
    if (threadIdx.x == 0) {
        float den = fmaxf(sqrtf(n1) * sqrtf(n2), 1e-8f);
        atomicAdd(out, (1.f - dp / den) * (1.f / (NN * BB)));
    }
}

// ---------------- host launcher ----------------
extern "C" void kernel_launch(void* const* d_in, const int* in_sizes, int n_in,
                              void* d_out, int out_size) {
    const float* base = (const float*)d_in[0];
    const float* Wbil = (const float*)d_in[1];
    const float* W1   = (const float*)d_in[2];
    const float* b1   = (const float*)d_in[3];
    const float* W2   = (const float*)d_in[4];
    const float* b2   = (const float*)d_in[5];
    const float* rootb= (const float*)d_in[6];
    float* out = (float*)d_out;

    cudaFuncSetAttribute(k_gemm2<0>, cudaFuncAttributeMaxDynamicSharedMemorySize, 65536);
    cudaFuncSetAttribute(k_gemm2<1>, cudaFuncAttributeMaxDynamicSharedMemorySize, 65536);

    float *p_iv, *p_ov, *p_P, *p_Po, *p_V, *p_isc, *p_osc;
    bf16 *p_Hb, *p_Wcatb, *p_W2b;
    cudaGetSymbolAddress((void**)&p_iv,  g_iv);
    cudaGetSymbolAddress((void**)&p_ov,  g_ov);
    cudaGetSymbolAddress((void**)&p_P,   g_P);
    cudaGetSymbolAddress((void**)&p_Po,  g_Po);
    cudaGetSymbolAddress((void**)&p_Hb,  g_Hb);
    cudaGetSymbolAddress((void**)&p_V,   g_V);
    cudaGetSymbolAddress((void**)&p_Wcatb, g_Wcatb);
    cudaGetSymbolAddress((void**)&p_W2b,   g_W2b);
    cudaGetSymbolAddress((void**)&p_isc, g_isc);
    cudaGetSymbolAddress((void**)&p_osc, g_osc);

    k_init_sc   <<<(TT * BB + 255) / 256, 256>>>();
    k_copy_base <<<(NN * BB * DD + 255) / 256, 256>>>(base);
    k_root      <<<(BB * DD + 255) / 256, 256>>>(rootb);
    k_build_wcat<<<(3 * DD * DD + 255) / 256, 256>>>(W1, Wbil);
    k_conv_w2   <<<(DD * DD + 255) / 256, 256>>>(W2);

    // projections for base cells
    k_gemm2<1><<<dim3(3 * DD / 128, (NN * BB + 127) / 128), 256, 65536>>>(
        p_iv, DD, p_Wcatb, DD, nullptr, p_P, 3 * DD, NN * BB, 3 * DD, DD, 0);

    // ---------------- inside pass ----------------
    for (int L = 2; L <= NN; L++) {
        int nb = NN + 1 - L, ns = L - 1;
        int M = nb * ns * BB;
        k_comb_inside<<<(M + 7) / 8, 256>>>(L, ns, M, b1);
        k_gemm2<0><<<dim3(DD / 128, (M + 127) / 128), 256, 65536>>>(
            p_Hb, DD, p_W2b, DD, b2, p_V, DD, M, DD, DD, 1);
        k_smx<<<nb * BB, 256>>>(ns, offL(L), p_V, p_iv, p_isc);
        if (L < NN) {
            size_t c0 = (size_t)offL(L);
            k_gemm2<1><<<dim3(3 * DD / 128, (nb * BB + 127) / 128), 256, 65536>>>(
                p_iv + c0 * BB * DD, DD, p_Wcatb, DD, nullptr,
                p_P + c0 * BB * 3 * DD, 3 * DD, nb * BB, 3 * DD, DD, 0);
        }
    }

    // root outside projection Po = ov_root @ W1a^T
    {
        size_t c0 = (size_t)offL(NN);
        k_gemm2<1><<<dim3(DD / 128, 1), 256, 65536>>>(
            p_ov + c0 * BB * DD, DD, p_Wcatb, DD, nullptr,
            p_Po + c0 * BB * DD, DD, BB, DD, DD, 0);
    }

    // ---------------- outside pass ----------------
    for (int L = NN - 1; L >= 1; L--) {
        int nb = NN + 1 - L, nso = NN - L;
        int M = nb * nso * BB;
        k_comb_outside<<<(M + 7) / 8, 256>>>(L, nso, M, b1);
        k_gemm2<0><<<dim3(DD / 128, (M + 127) / 128), 256, 65536>>>(
            p_Hb, DD, p_W2b, DD, b2, p_V, DD, M, DD, DD, 1);
        k_smx<<<nb * BB, 256>>>(nso, offL(L), p_V, p_ov, p_osc);
        if (L > 1) {
            size_t c0 = (size_t)offL(L);
            k_gemm2<1><<<dim3(DD / 128, (nb * BB + 127) / 128), 256, 65536>>>(
                p_ov + c0 * BB * DD, DD, p_Wcatb, DD, nullptr,
                p_Po + c0 * BB * DD, DD, nb * BB, DD, DD, 0);
        }
    }

    k_zero_out<<<1, 1>>>(out);
    k_loss<<<NN * BB, 256>>>(base, out);
}